// round 6
// baseline (speedup 1.0000x reference)
#include <cuda_runtime.h>
#include <cstdint>

// AttentionOutput: causal complex leaky-relu attention + linear head.
// B=4, N=4096, F=64.  mma.sync.m16n8k8.tf32, persistent CTAs + atomic work queue.

#define NT 256
#define STR 68      // padded stride (floats) for Q/K/W/Watt
#define VSTR 72     // padded stride for V
// smem offsets in floats (W aliases K: dead/alive phases are disjoint)
#define QR 0
#define QI 4352
#define KR 8704
#define KI 13056
#define VR 17408
#define VI 22016
#define SMF 26624
#define SMB (SMF * 4)   // 106496 bytes -> 2 CTAs/SM
#define WR KR
#define WI KI
#define WATT KR
#define BIAS KI

#define NITEMS 256      // 64 qtiles x 4 batches

__device__ int g_ctr;

__global__ void reset_ctr() { g_ctr = 0; }

__device__ __forceinline__ float rna(float x) {
    uint32_t u;
    asm("cvt.rna.tf32.f32 %0, %1;" : "=r"(u) : "f"(x));
    return __uint_as_float(u);
}

__device__ __forceinline__ void mma8(float* c, float a0, float a1, float a2, float a3,
                                     float b0, float b1) {
    uint32_t A0 = __float_as_uint(a0), A1 = __float_as_uint(a1);
    uint32_t A2 = __float_as_uint(a2), A3 = __float_as_uint(a3);
    uint32_t B0 = __float_as_uint(b0), B1 = __float_as_uint(b1);
    asm volatile("mma.sync.aligned.m16n8k8.row.col.f32.tf32.tf32.f32 "
                 "{%0,%1,%2,%3},{%4,%5,%6,%7},{%8,%9},{%0,%1,%2,%3};"
                 : "+f"(c[0]), "+f"(c[1]), "+f"(c[2]), "+f"(c[3])
                 : "r"(A0), "r"(A1), "r"(A2), "r"(A3), "r"(B0), "r"(B1));
}

#define LDQUAD(arr, base, v0, v1, v2, v3)                                   \
    float v0 = sm[(arr) + (base)];                                          \
    float v1 = sm[(arr) + (base) + 8 * STR];                                \
    float v2 = sm[(arr) + (base) + 4];                                      \
    float v3 = sm[(arr) + (base) + 8 * STR + 4];

#define SPLIT4(x0, x1, x2, x3, h0, h1, h2, h3, l0, l1, l2, l3)              \
    float h0 = rna(x0), h1 = rna(x1), h2 = rna(x2), h3 = rna(x3);           \
    float l0 = x0 - h0, l1 = x1 - h1, l2 = x2 - h2, l3 = x3 - h3;

__global__ __launch_bounds__(NT, 2)
void attn_k(const float2* __restrict__ Qg, const float2* __restrict__ Kg,
            const float2* __restrict__ Vg, const float* __restrict__ Wg,
            const float* __restrict__ bg, float2* __restrict__ Og)
{
    extern __shared__ float sm[];
    __shared__ int s_item;
    const int tid = threadIdx.x, w = tid >> 5, l = tid & 31;
    const int g = l >> 2, t = l & 3;
    const int N = 4096;

    const int i0w = (w >> 1) * 16, j0w = (w & 1) * 32;     // phase-1 warp map
    const int i0p = (w & 3) * 16, f0p = (w >> 2) * 32;     // phase-2 warp map
    const float scale = 1.0f / 64.0f;                      // 1/sqrt(4096)

    for (;;) {
        __syncthreads();   // previous item's smem reads done; s_item reusable
        if (tid == 0) s_item = atomicAdd(&g_ctr, 1);
        __syncthreads();
        const int item = s_item;
        if (item >= NITEMS) break;

        const int b = item & 3;
        const int qt = 63 - (item >> 2);    // heavy items first
        const int qi0 = qt * 64;

        // ---- load Q tile (fp32) ----
        {
            const float2* Qp = Qg + ((size_t)b * N + qi0) * 64;
            for (int idx = tid; idx < 64 * 64; idx += NT) {
                float2 q = Qp[idx];
                int a = (idx >> 6) * STR + (idx & 63);
                sm[QR + a] = q.x; sm[QI + a] = q.y;
            }
        }

        float o_r[4][4], o_i[4][4];
        #pragma unroll
        for (int nb = 0; nb < 4; ++nb)
            #pragma unroll
            for (int r = 0; r < 4; ++r) { o_r[nb][r] = 0.f; o_i[nb][r] = 0.f; }

        for (int tt = 0; tt <= qt; ++tt) {
            const int kt = tt * 64;
            __syncthreads();   // prior phase-2 reads of V/W done (W aliases K)

            // ---- load K (fp32) and V (tf32) ----
            {
                const float2* Kp = Kg + ((size_t)b * N + kt) * 64;
                const float2* Vp = Vg + ((size_t)b * N + kt) * 64;
                for (int idx = tid; idx < 64 * 64; idx += NT) {
                    float2 kv = Kp[idx];
                    float2 vv = Vp[idx];
                    int j = idx >> 6, f = idx & 63;
                    sm[KR + j * STR + f] = kv.x;
                    sm[KI + j * STR + f] = kv.y;
                    sm[VR + j * VSTR + f] = rna(vv.x);
                    sm[VI + j * VSTR + f] = rna(vv.y);
                }
            }
            __syncthreads();

            // ---- phase 1: Crr, Cii, Css (Karatsuba, 3xTF32 each) ----
            float crr[4][4], cii[4][4], css[4][4];
            #pragma unroll
            for (int nb = 0; nb < 4; ++nb)
                #pragma unroll
                for (int r = 0; r < 4; ++r) { crr[nb][r] = 0.f; cii[nb][r] = 0.f; css[nb][r] = 0.f; }

            for (int kk = 0; kk < 8; ++kk) {
                const int k0 = kk * 8;
                const int ab = (i0w + g) * STR + k0 + t;
                LDQUAD(QR, ab, xr0, xr1, xr2, xr3)
                LDQUAD(QI, ab, xi0, xi1, xi2, xi3)
                SPLIT4(xr0, xr1, xr2, xr3, qrh0, qrh1, qrh2, qrh3, qrl0, qrl1, qrl2, qrl3)
                SPLIT4(xi0, xi1, xi2, xi3, qih0, qih1, qih2, qih3, qil0, qil1, qil2, qil3)
                float xs0 = xr0 + xi0, xs1 = xr1 + xi1, xs2 = xr2 + xi2, xs3 = xr3 + xi3;
                SPLIT4(xs0, xs1, xs2, xs3, qsh0, qsh1, qsh2, qsh3, qsl0, qsl1, qsl2, qsl3)
                #pragma unroll
                for (int nb = 0; nb < 4; ++nb) {
                    const int bb = (j0w + nb * 8 + g) * STR + k0 + t;
                    float yr0 = sm[KR + bb], yr1 = sm[KR + bb + 4];
                    float yi0 = sm[KI + bb], yi1 = sm[KI + bb + 4];
                    float krh0 = rna(yr0), krl0 = yr0 - krh0;
                    float krh1 = rna(yr1), krl1 = yr1 - krh1;
                    float kih0 = rna(yi0), kil0 = yi0 - kih0;
                    float kih1 = rna(yi1), kil1 = yi1 - kih1;
                    float ys0 = yr0 + yi0, ys1 = yr1 + yi1;
                    float ksh0 = rna(ys0), ksl0 = ys0 - ksh0;
                    float ksh1 = rna(ys1), ksl1 = ys1 - ksh1;
                    mma8(crr[nb], qrh0, qrh1, qrh2, qrh3, krh0, krh1);
                    mma8(crr[nb], qrl0, qrl1, qrl2, qrl3, krh0, krh1);
                    mma8(crr[nb], qrh0, qrh1, qrh2, qrh3, krl0, krl1);
                    mma8(cii[nb], qih0, qih1, qih2, qih3, kih0, kih1);
                    mma8(cii[nb], qil0, qil1, qil2, qil3, kih0, kih1);
                    mma8(cii[nb], qih0, qih1, qih2, qih3, kil0, kil1);
                    mma8(css[nb], qsh0, qsh1, qsh2, qsh3, ksh0, ksh1);
                    mma8(css[nb], qsl0, qsl1, qsl2, qsl3, ksh0, ksh1);
                    mma8(css[nb], qsh0, qsh1, qsh2, qsh3, ksl0, ksl1);
                }
            }

            __syncthreads();   // all phase-1 K reads done before W overwrites K region

            // ---- epilogue: scale + leaky + causal mask -> W (fp32, aliased on K) ----
            #pragma unroll
            for (int nb = 0; nb < 4; ++nb) {
                float vr_[4], vi_[4];
                #pragma unroll
                for (int r = 0; r < 4; ++r) {
                    int il = i0w + g + ((r & 2) ? 8 : 0);
                    int jg = kt + j0w + nb * 8 + 2 * t + (r & 1);
                    float sr = (crr[nb][r] - cii[nb][r]) * scale;
                    float si = (css[nb][r] - crr[nb][r] - cii[nb][r]) * scale;
                    sr = sr >= 0.f ? sr : 0.01f * sr;
                    si = si >= 0.f ? si : 0.01f * si;
                    if (jg > qi0 + il) { sr = 0.f; si = 0.f; }
                    vr_[r] = sr; vi_[r] = si;
                }
                int wb = (i0w + g) * STR + j0w + nb * 8 + 2 * t;
                *(float2*)&sm[WR + wb]           = make_float2(vr_[0], vr_[1]);
                *(float2*)&sm[WR + wb + 8 * STR] = make_float2(vr_[2], vr_[3]);
                *(float2*)&sm[WI + wb]           = make_float2(vi_[0], vi_[1]);
                *(float2*)&sm[WI + wb + 8 * STR] = make_float2(vi_[2], vi_[3]);
            }
            __syncthreads();

            // ---- phase 2: O += W V (W hi/lo, V tf32) ----
            for (int kk = 0; kk < 8; ++kk) {
                const int k0 = kk * 8;
                const int ab = (i0p + g) * STR + k0 + t;
                LDQUAD(WR, ab, zr0, zr1, zr2, zr3)
                LDQUAD(WI, ab, zi0, zi1, zi2, zi3)
                SPLIT4(zr0, zr1, zr2, zr3, wrh0, wrh1, wrh2, wrh3, wrl0, wrl1, wrl2, wrl3)
                SPLIT4(zi0, zi1, zi2, zi3, wih0, wih1, wih2, wih3, wil0, wil1, wil2, wil3)
                #pragma unroll
                for (int nb = 0; nb < 4; ++nb) {
                    const int vb = (k0 + t) * VSTR + f0p + nb * 8 + g;
                    float v0 = sm[VR + vb], v1 = sm[VR + vb + 4 * VSTR];
                    float u0 = sm[VI + vb], u1 = sm[VI + vb + 4 * VSTR];
                    mma8(o_r[nb], wrh0, wrh1, wrh2, wrh3, v0, v1);
                    mma8(o_r[nb], wrl0, wrl1, wrl2, wrl3, v0, v1);
                    mma8(o_i[nb], wih0, wih1, wih2, wih3, u0, u1);
                    mma8(o_i[nb], wil0, wil1, wil2, wil3, u0, u1);
                }
            }
        }

        // ---- linear head via mma: out = O @ Watt^T + b ----
        __syncthreads();   // all phase-2 done before overwriting Q/K regions
        #pragma unroll
        for (int nb = 0; nb < 4; ++nb)
            #pragma unroll
            for (int r = 0; r < 4; ++r) {
                int il = i0p + g + ((r & 2) ? 8 : 0);
                int fo = f0p + nb * 8 + 2 * t + (r & 1);
                sm[QR + il * STR + fo] = o_r[nb][r];
                sm[QI + il * STR + fo] = o_i[nb][r];
            }
        for (int idx = tid; idx < 64 * 64; idx += NT)
            sm[WATT + (idx >> 6) * STR + (idx & 63)] = Wg[idx];
        if (tid < 64) sm[BIAS + tid] = bg[tid];
        __syncthreads();

        float hr[4][4], hi_[4][4];
        #pragma unroll
        for (int nb = 0; nb < 4; ++nb)
            #pragma unroll
            for (int r = 0; r < 4; ++r) { hr[nb][r] = 0.f; hi_[nb][r] = 0.f; }

        for (int kk = 0; kk < 8; ++kk) {
            const int k0 = kk * 8;
            const int ab = (i0p + g) * STR + k0 + t;
            LDQUAD(QR, ab, pr0, pr1, pr2, pr3)
            LDQUAD(QI, ab, pi0, pi1, pi2, pi3)
            SPLIT4(pr0, pr1, pr2, pr3, orh0, orh1, orh2, orh3, orl0, orl1, orl2, orl3)
            SPLIT4(pi0, pi1, pi2, pi3, oih0, oih1, oih2, oih3, oil0, oil1, oil2, oil3)
            #pragma unroll
            for (int nb = 0; nb < 4; ++nb) {
                const int wb2 = (f0p + nb * 8 + g) * STR + k0 + t;
                float w0 = sm[WATT + wb2], w1 = sm[WATT + wb2 + 4];
                float wh0 = rna(w0), wl0 = w0 - wh0;
                float wh1 = rna(w1), wl1 = w1 - wh1;
                mma8(hr[nb], orh0, orh1, orh2, orh3, wh0, wh1);
                mma8(hr[nb], orl0, orl1, orl2, orl3, wh0, wh1);
                mma8(hr[nb], orh0, orh1, orh2, orh3, wl0, wl1);
                mma8(hi_[nb], oih0, oih1, oih2, oih3, wh0, wh1);
                mma8(hi_[nb], oil0, oil1, oil2, oil3, wh0, wh1);
                mma8(hi_[nb], oih0, oih1, oih2, oih3, wl0, wl1);
            }
        }

        float2* Ob = Og + ((size_t)b * N + qi0) * 64;
        #pragma unroll
        for (int nb = 0; nb < 4; ++nb)
            #pragma unroll
            for (int r = 0; r < 4; ++r) {
                int il = i0p + g + ((r & 2) ? 8 : 0);
                int fo = f0p + nb * 8 + 2 * t + (r & 1);
                float bb = sm[BIAS + fo];
                Ob[il * 64 + fo] = make_float2(hr[nb][r] + bb, hi_[nb][r] + bb);
            }
    }
}

extern "C" void kernel_launch(void* const* d_in, const int* in_sizes, int n_in,
                              void* d_out, int out_size)
{
    const float2* Q = (const float2*)d_in[0];
    const float2* K = (const float2*)d_in[1];
    const float2* V = (const float2*)d_in[2];
    const float*  W = (const float*)d_in[3];
    const float*  bb = (const float*)d_in[4];
    float2* O = (float2*)d_out;

    static bool attr_set = false;
    if (!attr_set) {
        cudaFuncSetAttribute(attn_k, cudaFuncAttributeMaxDynamicSharedMemorySize, SMB);
        attr_set = true;
    }

    reset_ctr<<<1, 1>>>();
    attn_k<<<dim3(296, 1), NT, SMB>>>(Q, K, V, W, bb, O);
}

// round 7
// speedup vs baseline: 2.0806x; 2.0806x over previous
#include <cuda_runtime.h>
#include <cstdint>

// AttentionOutput: causal complex leaky-relu attention + linear head.
// B=4, N=4096, F=64.  mma.sync.m16n8k8.tf32, single-pass tf32 QK, 2xTF32 PV.

#define NT 256
#define STR 68      // padded stride (floats) for Q/K/W/Watt
#define VSTR 72     // padded stride for V
// smem offsets in floats (W aliases K: disjoint live ranges)
#define QR 0
#define QI 4352
#define KR 8704
#define KI 13056
#define VR 17408
#define VI 22016
#define SMF 26624
#define SMB (SMF * 4)   // 106496 bytes -> 2 CTAs/SM
#define WR KR
#define WI KI
#define WATT KR
#define BIAS KI

__device__ __forceinline__ float rna(float x) {
    uint32_t u;
    asm("cvt.rna.tf32.f32 %0, %1;" : "=r"(u) : "f"(x));
    return __uint_as_float(u);
}

__device__ __forceinline__ void mma8(float* c, float a0, float a1, float a2, float a3,
                                     float b0, float b1) {
    uint32_t A0 = __float_as_uint(a0), A1 = __float_as_uint(a1);
    uint32_t A2 = __float_as_uint(a2), A3 = __float_as_uint(a3);
    uint32_t B0 = __float_as_uint(b0), B1 = __float_as_uint(b1);
    asm volatile("mma.sync.aligned.m16n8k8.row.col.f32.tf32.tf32.f32 "
                 "{%0,%1,%2,%3},{%4,%5,%6,%7},{%8,%9},{%0,%1,%2,%3};"
                 : "+f"(c[0]), "+f"(c[1]), "+f"(c[2]), "+f"(c[3])
                 : "r"(A0), "r"(A1), "r"(A2), "r"(A3), "r"(B0), "r"(B1));
}

#define LDQUAD(arr, base, v0, v1, v2, v3)                                   \
    float v0 = sm[(arr) + (base)];                                          \
    float v1 = sm[(arr) + (base) + 8 * STR];                                \
    float v2 = sm[(arr) + (base) + 4];                                      \
    float v3 = sm[(arr) + (base) + 8 * STR + 4];

#define SPLIT4(x0, x1, x2, x3, h0, h1, h2, h3, l0, l1, l2, l3)              \
    float h0 = rna(x0), h1 = rna(x1), h2 = rna(x2), h3 = rna(x3);           \
    float l0 = x0 - h0, l1 = x1 - h1, l2 = x2 - h2, l3 = x3 - h3;

__global__ __launch_bounds__(NT, 2)
void attn_k(const float2* __restrict__ Qg, const float2* __restrict__ Kg,
            const float2* __restrict__ Vg, const float* __restrict__ Wg,
            const float* __restrict__ bg, float2* __restrict__ Og)
{
    extern __shared__ float sm[];
    const int tid = threadIdx.x, w = tid >> 5, l = tid & 31;
    const int g = l >> 2, t = l & 3;
    const int b = blockIdx.y;
    const int qt = (int)gridDim.x - 1 - (int)blockIdx.x;   // heavy tiles first
    const int qi0 = qt * 64;
    const int N = 4096;

    const int i0w = (w >> 1) * 16, j0w = (w & 1) * 32;     // phase-1 warp map
    const int i0p = (w & 3) * 16, f0p = (w >> 2) * 32;     // phase-2 warp map
    const float scale = 1.0f / 64.0f;                      // 1/sqrt(4096)

    // ---- load Q tile (pre-rounded tf32) ----
    {
        const float2* Qp = Qg + ((size_t)b * N + qi0) * 64;
        for (int idx = tid; idx < 64 * 64; idx += NT) {
            float2 q = Qp[idx];
            int a = (idx >> 6) * STR + (idx & 63);
            sm[QR + a] = rna(q.x); sm[QI + a] = rna(q.y);
        }
    }

    float o_r[4][4], o_i[4][4];
    #pragma unroll
    for (int nb = 0; nb < 4; ++nb)
        #pragma unroll
        for (int r = 0; r < 4; ++r) { o_r[nb][r] = 0.f; o_i[nb][r] = 0.f; }

    for (int tt = 0; tt <= qt; ++tt) {
        const int kt = tt * 64;
        __syncthreads();   // prior phase-2 reads of V/W done (W aliases K)

        // ---- load K, V (pre-rounded tf32) ----
        {
            const float2* Kp = Kg + ((size_t)b * N + kt) * 64;
            const float2* Vp = Vg + ((size_t)b * N + kt) * 64;
            for (int idx = tid; idx < 64 * 64; idx += NT) {
                float2 kv = Kp[idx];
                float2 vv = Vp[idx];
                int j = idx >> 6, f = idx & 63;
                sm[KR + j * STR + f] = rna(kv.x);
                sm[KI + j * STR + f] = rna(kv.y);
                sm[VR + j * VSTR + f] = rna(vv.x);
                sm[VI + j * VSTR + f] = rna(vv.y);
            }
        }
        __syncthreads();

        // ---- phase 1: crr = QrKr, cii = QiKi, csi = QrKi + QiKr (tf32) ----
        float crr[4][4], cii[4][4], csi[4][4];
        #pragma unroll
        for (int nb = 0; nb < 4; ++nb)
            #pragma unroll
            for (int r = 0; r < 4; ++r) { crr[nb][r] = 0.f; cii[nb][r] = 0.f; csi[nb][r] = 0.f; }

        for (int kk = 0; kk < 8; ++kk) {
            const int k0 = kk * 8;
            const int ab = (i0w + g) * STR + k0 + t;
            LDQUAD(QR, ab, qr0, qr1, qr2, qr3)
            LDQUAD(QI, ab, qi0_, qi1, qi2, qi3)
            #pragma unroll
            for (int nb = 0; nb < 4; ++nb) {
                const int bb = (j0w + nb * 8 + g) * STR + k0 + t;
                float kr0 = sm[KR + bb], kr1 = sm[KR + bb + 4];
                float ki0 = sm[KI + bb], ki1 = sm[KI + bb + 4];
                mma8(crr[nb], qr0, qr1, qr2, qr3, kr0, kr1);
                mma8(cii[nb], qi0_, qi1, qi2, qi3, ki0, ki1);
                mma8(csi[nb], qr0, qr1, qr2, qr3, ki0, ki1);
                mma8(csi[nb], qi0_, qi1, qi2, qi3, kr0, kr1);
            }
        }

        __syncthreads();   // all phase-1 K reads done before W overwrites K region

        // ---- epilogue: scale + leaky + causal mask -> W (fp32, aliased on K) ----
        #pragma unroll
        for (int nb = 0; nb < 4; ++nb) {
            float vr_[4], vi_[4];
            #pragma unroll
            for (int r = 0; r < 4; ++r) {
                int il = i0w + g + ((r & 2) ? 8 : 0);
                int jg = kt + j0w + nb * 8 + 2 * t + (r & 1);
                float sr = (crr[nb][r] - cii[nb][r]) * scale;
                float si = csi[nb][r] * scale;
                sr = sr >= 0.f ? sr : 0.01f * sr;
                si = si >= 0.f ? si : 0.01f * si;
                if (jg > qi0 + il) { sr = 0.f; si = 0.f; }
                vr_[r] = sr; vi_[r] = si;
            }
            int wb = (i0w + g) * STR + j0w + nb * 8 + 2 * t;
            *(float2*)&sm[WR + wb]           = make_float2(vr_[0], vr_[1]);
            *(float2*)&sm[WR + wb + 8 * STR] = make_float2(vr_[2], vr_[3]);
            *(float2*)&sm[WI + wb]           = make_float2(vi_[0], vi_[1]);
            *(float2*)&sm[WI + wb + 8 * STR] = make_float2(vi_[2], vi_[3]);
        }
        __syncthreads();

        // ---- phase 2: O += W V (W hi/lo split on the fly, V tf32) ----
        for (int kk = 0; kk < 8; ++kk) {
            const int k0 = kk * 8;
            const int ab = (i0p + g) * STR + k0 + t;
            LDQUAD(WR, ab, zr0, zr1, zr2, zr3)
            LDQUAD(WI, ab, zi0, zi1, zi2, zi3)
            SPLIT4(zr0, zr1, zr2, zr3, wrh0, wrh1, wrh2, wrh3, wrl0, wrl1, wrl2, wrl3)
            SPLIT4(zi0, zi1, zi2, zi3, wih0, wih1, wih2, wih3, wil0, wil1, wil2, wil3)
            #pragma unroll
            for (int nb = 0; nb < 4; ++nb) {
                const int vb = (k0 + t) * VSTR + f0p + nb * 8 + g;
                float v0 = sm[VR + vb], v1 = sm[VR + vb + 4 * VSTR];
                float u0 = sm[VI + vb], u1 = sm[VI + vb + 4 * VSTR];
                mma8(o_r[nb], wrh0, wrh1, wrh2, wrh3, v0, v1);
                mma8(o_r[nb], wrl0, wrl1, wrl2, wrl3, v0, v1);
                mma8(o_i[nb], wih0, wih1, wih2, wih3, u0, u1);
                mma8(o_i[nb], wil0, wil1, wil2, wil3, u0, u1);
            }
        }
    }

    // ---- linear head via mma: out = O @ Watt^T + b ----
    __syncthreads();   // all phase-2 done before overwriting Q/K regions
    #pragma unroll
    for (int nb = 0; nb < 4; ++nb)
        #pragma unroll
        for (int r = 0; r < 4; ++r) {
            int il = i0p + g + ((r & 2) ? 8 : 0);
            int fo = f0p + nb * 8 + 2 * t + (r & 1);
            sm[QR + il * STR + fo] = o_r[nb][r];
            sm[QI + il * STR + fo] = o_i[nb][r];
        }
    for (int idx = tid; idx < 64 * 64; idx += NT)
        sm[WATT + (idx >> 6) * STR + (idx & 63)] = Wg[idx];
    if (tid < 64) sm[BIAS + tid] = bg[tid];
    __syncthreads();

    float hr[4][4], hi_[4][4];
    #pragma unroll
    for (int nb = 0; nb < 4; ++nb)
        #pragma unroll
        for (int r = 0; r < 4; ++r) { hr[nb][r] = 0.f; hi_[nb][r] = 0.f; }

    for (int kk = 0; kk < 8; ++kk) {
        const int k0 = kk * 8;
        const int ab = (i0p + g) * STR + k0 + t;
        LDQUAD(QR, ab, pr0, pr1, pr2, pr3)
        LDQUAD(QI, ab, pi0, pi1, pi2, pi3)
        SPLIT4(pr0, pr1, pr2, pr3, orh0, orh1, orh2, orh3, orl0, orl1, orl2, orl3)
        SPLIT4(pi0, pi1, pi2, pi3, oih0, oih1, oih2, oih3, oil0, oil1, oil2, oil3)
        #pragma unroll
        for (int nb = 0; nb < 4; ++nb) {
            const int wb2 = (f0p + nb * 8 + g) * STR + k0 + t;
            float w0 = sm[WATT + wb2], w1 = sm[WATT + wb2 + 4];
            float wh0 = rna(w0), wl0 = w0 - wh0;
            float wh1 = rna(w1), wl1 = w1 - wh1;
            mma8(hr[nb], orh0, orh1, orh2, orh3, wh0, wh1);
            mma8(hr[nb], orl0, orl1, orl2, orl3, wh0, wh1);
            mma8(hr[nb], orh0, orh1, orh2, orh3, wl0, wl1);
            mma8(hi_[nb], oih0, oih1, oih2, oih3, wh0, wh1);
            mma8(hi_[nb], oil0, oil1, oil2, oil3, wh0, wh1);
            mma8(hi_[nb], oih0, oih1, oih2, oih3, wl0, wl1);
        }
    }

    float2* Ob = Og + ((size_t)b * N + qi0) * 64;
    #pragma unroll
    for (int nb = 0; nb < 4; ++nb)
        #pragma unroll
        for (int r = 0; r < 4; ++r) {
            int il = i0p + g + ((r & 2) ? 8 : 0);
            int fo = f0p + nb * 8 + 2 * t + (r & 1);
            float bb = sm[BIAS + fo];
            Ob[il * 64 + fo] = make_float2(hr[nb][r] + bb, hi_[nb][r] + bb);
        }
}

extern "C" void kernel_launch(void* const* d_in, const int* in_sizes, int n_in,
                              void* d_out, int out_size)
{
    const float2* Q = (const float2*)d_in[0];
    const float2* K = (const float2*)d_in[1];
    const float2* V = (const float2*)d_in[2];
    const float*  W = (const float*)d_in[3];
    const float*  bb = (const float*)d_in[4];
    float2* O = (float2*)d_out;

    static bool attr_set = false;
    if (!attr_set) {
        cudaFuncSetAttribute(attn_k, cudaFuncAttributeMaxDynamicSharedMemorySize, SMB);
        attr_set = true;
    }

    attn_k<<<dim3(64, 4), NT, SMB>>>(Q, K, V, W, bb, O);
}

// round 8
// speedup vs baseline: 3.1658x; 1.5216x over previous
#include <cuda_runtime.h>
#include <cstdint>

// AttentionOutput: causal complex leaky-relu attention + linear head.
// B=4, N=4096, F=64.  mma.sync.m16n8k8.tf32; complementary-pair CTA balance.

#define NT 256
#define STR 68      // padded stride (floats) for Q/K/W/Watt
#define VSTR 72     // padded stride for V
// smem offsets in floats (all regions separate; 1 CTA/SM)
#define QR 0
#define QI 4352
#define KR 8704
#define KI 13056
#define VR 17408
#define VI 22016
#define WR 26624
#define WI 30976
#define SMF 35328
#define SMB (SMF * 4)   // 141312 bytes
#define WATT KR
#define BIAS KI

__device__ __forceinline__ float rna(float x) {
    uint32_t u;
    asm("cvt.rna.tf32.f32 %0, %1;" : "=r"(u) : "f"(x));
    return __uint_as_float(u);
}

__device__ __forceinline__ void mma8(float* c, float a0, float a1, float a2, float a3,
                                     float b0, float b1) {
    uint32_t A0 = __float_as_uint(a0), A1 = __float_as_uint(a1);
    uint32_t A2 = __float_as_uint(a2), A3 = __float_as_uint(a3);
    uint32_t B0 = __float_as_uint(b0), B1 = __float_as_uint(b1);
    asm volatile("mma.sync.aligned.m16n8k8.row.col.f32.tf32.tf32.f32 "
                 "{%0,%1,%2,%3},{%4,%5,%6,%7},{%8,%9},{%0,%1,%2,%3};"
                 : "+f"(c[0]), "+f"(c[1]), "+f"(c[2]), "+f"(c[3])
                 : "r"(A0), "r"(A1), "r"(A2), "r"(A3), "r"(B0), "r"(B1));
}

#define LDQUAD(arr, base, v0, v1, v2, v3)                                   \
    float v0 = sm[(arr) + (base)];                                          \
    float v1 = sm[(arr) + (base) + 8 * STR];                                \
    float v2 = sm[(arr) + (base) + 4];                                      \
    float v3 = sm[(arr) + (base) + 8 * STR + 4];

#define SPLIT4(x0, x1, x2, x3, h0, h1, h2, h3, l0, l1, l2, l3)              \
    float h0 = rna(x0), h1 = rna(x1), h2 = rna(x2), h3 = rna(x3);           \
    float l0 = x0 - h0, l1 = x1 - h1, l2 = x2 - h2, l3 = x3 - h3;

__global__ __launch_bounds__(NT)
void attn_k(const float2* __restrict__ Qg, const float2* __restrict__ Kg,
            const float2* __restrict__ Vg, const float* __restrict__ Wg,
            const float* __restrict__ bg, float2* __restrict__ Og)
{
    extern __shared__ float sm[];
    const int tid = threadIdx.x, w = tid >> 5, l = tid & 31;
    const int g = l >> 2, t = l & 3;
    const int b = blockIdx.y;
    const int N = 4096;

    const int i0w = (w >> 1) * 16, j0w = (w & 1) * 32;     // phase-1 warp map
    const int i0p = (w & 3) * 16, f0p = (w >> 2) * 32;     // phase-2 warp map
    const float scale = 1.0f / 64.0f;                      // 1/sqrt(4096)

    // complementary pair: work (bx+1) + (64-bx) = 65 tile-units, all CTAs equal
    #pragma unroll 1
    for (int pi = 0; pi < 2; ++pi) {
        const int qt = pi ? (63 - (int)blockIdx.x) : (int)blockIdx.x;
        const int qi0 = qt * 64;

        __syncthreads();   // previous pair's epilogue smem reads done

        // ---- load Q tile (pre-rounded tf32) ----
        {
            const float2* Qp = Qg + ((size_t)b * N + qi0) * 64;
            for (int idx = tid; idx < 64 * 64; idx += NT) {
                float2 q = Qp[idx];
                int a = (idx >> 6) * STR + (idx & 63);
                sm[QR + a] = rna(q.x); sm[QI + a] = rna(q.y);
            }
        }

        float o_r[4][4], o_i[4][4];
        #pragma unroll
        for (int nb = 0; nb < 4; ++nb)
            #pragma unroll
            for (int r = 0; r < 4; ++r) { o_r[nb][r] = 0.f; o_i[nb][r] = 0.f; }

        for (int tt = 0; tt <= qt; ++tt) {
            const int kt = tt * 64;
            __syncthreads();   // prior phase-2 reads of V/W done

            // ---- load K, V (pre-rounded tf32) ----
            {
                const float2* Kp = Kg + ((size_t)b * N + kt) * 64;
                const float2* Vp = Vg + ((size_t)b * N + kt) * 64;
                for (int idx = tid; idx < 64 * 64; idx += NT) {
                    float2 kv = Kp[idx];
                    float2 vv = Vp[idx];
                    int j = idx >> 6, f = idx & 63;
                    sm[KR + j * STR + f] = rna(kv.x);
                    sm[KI + j * STR + f] = rna(kv.y);
                    sm[VR + j * VSTR + f] = rna(vv.x);
                    sm[VI + j * VSTR + f] = rna(vv.y);
                }
            }
            __syncthreads();

            // ---- phase 1: crr = QrKr, cii = QiKi, csi = QrKi + QiKr ----
            float crr[4][4], cii[4][4], csi[4][4];
            #pragma unroll
            for (int nb = 0; nb < 4; ++nb)
                #pragma unroll
                for (int r = 0; r < 4; ++r) { crr[nb][r] = 0.f; cii[nb][r] = 0.f; csi[nb][r] = 0.f; }

            for (int kk = 0; kk < 8; ++kk) {
                const int k0 = kk * 8;
                const int ab = (i0w + g) * STR + k0 + t;
                LDQUAD(QR, ab, qr0, qr1, qr2, qr3)
                LDQUAD(QI, ab, qi0_, qi1, qi2, qi3)
                #pragma unroll
                for (int nb = 0; nb < 4; ++nb) {
                    const int bb = (j0w + nb * 8 + g) * STR + k0 + t;
                    float kr0 = sm[KR + bb], kr1 = sm[KR + bb + 4];
                    float ki0 = sm[KI + bb], ki1 = sm[KI + bb + 4];
                    mma8(crr[nb], qr0, qr1, qr2, qr3, kr0, kr1);
                    mma8(cii[nb], qi0_, qi1, qi2, qi3, ki0, ki1);
                    mma8(csi[nb], qr0, qr1, qr2, qr3, ki0, ki1);
                    mma8(csi[nb], qi0_, qi1, qi2, qi3, kr0, kr1);
                }
            }

            // ---- epilogue: scale + leaky + mask -> W (pre-rounded tf32) ----
            #pragma unroll
            for (int nb = 0; nb < 4; ++nb) {
                float vr_[4], vi_[4];
                #pragma unroll
                for (int r = 0; r < 4; ++r) {
                    int il = i0w + g + ((r & 2) ? 8 : 0);
                    int jg = kt + j0w + nb * 8 + 2 * t + (r & 1);
                    float sr = (crr[nb][r] - cii[nb][r]) * scale;
                    float si = csi[nb][r] * scale;
                    sr = sr >= 0.f ? sr : 0.01f * sr;
                    si = si >= 0.f ? si : 0.01f * si;
                    if (jg > qi0 + il) { sr = 0.f; si = 0.f; }
                    vr_[r] = rna(sr); vi_[r] = rna(si);
                }
                int wb = (i0w + g) * STR + j0w + nb * 8 + 2 * t;
                *(float2*)&sm[WR + wb]           = make_float2(vr_[0], vr_[1]);
                *(float2*)&sm[WR + wb + 8 * STR] = make_float2(vr_[2], vr_[3]);
                *(float2*)&sm[WI + wb]           = make_float2(vi_[0], vi_[1]);
                *(float2*)&sm[WI + wb + 8 * STR] = make_float2(vi_[2], vi_[3]);
            }
            __syncthreads();

            // ---- phase 2: O += W V (single-pass tf32) ----
            for (int kk = 0; kk < 8; ++kk) {
                const int k0 = kk * 8;
                const int ab = (i0p + g) * STR + k0 + t;
                LDQUAD(WR, ab, wr0, wr1, wr2, wr3)
                LDQUAD(WI, ab, wi0, wi1, wi2, wi3)
                #pragma unroll
                for (int nb = 0; nb < 4; ++nb) {
                    const int vb = (k0 + t) * VSTR + f0p + nb * 8 + g;
                    float v0 = sm[VR + vb], v1 = sm[VR + vb + 4 * VSTR];
                    float u0 = sm[VI + vb], u1 = sm[VI + vb + 4 * VSTR];
                    mma8(o_r[nb], wr0, wr1, wr2, wr3, v0, v1);
                    mma8(o_i[nb], wi0, wi1, wi2, wi3, u0, u1);
                }
            }
        }

        // ---- linear head via mma: out = O @ Watt^T + b ----
        __syncthreads();   // all phase-2 done before overwriting Q/K regions
        #pragma unroll
        for (int nb = 0; nb < 4; ++nb)
            #pragma unroll
            for (int r = 0; r < 4; ++r) {
                int il = i0p + g + ((r & 2) ? 8 : 0);
                int fo = f0p + nb * 8 + 2 * t + (r & 1);
                sm[QR + il * STR + fo] = o_r[nb][r];
                sm[QI + il * STR + fo] = o_i[nb][r];
            }
        for (int idx = tid; idx < 64 * 64; idx += NT)
            sm[WATT + (idx >> 6) * STR + (idx & 63)] = Wg[idx];
        if (tid < 64) sm[BIAS + tid] = bg[tid];
        __syncthreads();

        float hr[4][4], hi_[4][4];
        #pragma unroll
        for (int nb = 0; nb < 4; ++nb)
            #pragma unroll
            for (int r = 0; r < 4; ++r) { hr[nb][r] = 0.f; hi_[nb][r] = 0.f; }

        for (int kk = 0; kk < 8; ++kk) {
            const int k0 = kk * 8;
            const int ab = (i0p + g) * STR + k0 + t;
            LDQUAD(QR, ab, pr0, pr1, pr2, pr3)
            LDQUAD(QI, ab, pi0, pi1, pi2, pi3)
            SPLIT4(pr0, pr1, pr2, pr3, orh0, orh1, orh2, orh3, orl0, orl1, orl2, orl3)
            SPLIT4(pi0, pi1, pi2, pi3, oih0, oih1, oih2, oih3, oil0, oil1, oil2, oil3)
            #pragma unroll
            for (int nb = 0; nb < 4; ++nb) {
                const int wb2 = (f0p + nb * 8 + g) * STR + k0 + t;
                float w0 = sm[WATT + wb2], w1 = sm[WATT + wb2 + 4];
                float wh0 = rna(w0), wl0 = w0 - wh0;
                float wh1 = rna(w1), wl1 = w1 - wh1;
                mma8(hr[nb], orh0, orh1, orh2, orh3, wh0, wh1);
                mma8(hr[nb], orl0, orl1, orl2, orl3, wh0, wh1);
                mma8(hr[nb], orh0, orh1, orh2, orh3, wl0, wl1);
                mma8(hi_[nb], oih0, oih1, oih2, oih3, wh0, wh1);
                mma8(hi_[nb], oil0, oil1, oil2, oil3, wh0, wh1);
                mma8(hi_[nb], oih0, oih1, oih2, oih3, wl0, wl1);
            }
        }

        float2* Ob = Og + ((size_t)b * N + qi0) * 64;
        #pragma unroll
        for (int nb = 0; nb < 4; ++nb)
            #pragma unroll
            for (int r = 0; r < 4; ++r) {
                int il = i0p + g + ((r & 2) ? 8 : 0);
                int fo = f0p + nb * 8 + 2 * t + (r & 1);
                float bb = sm[BIAS + fo];
                Ob[il * 64 + fo] = make_float2(hr[nb][r] + bb, hi_[nb][r] + bb);
            }
    }
}

extern "C" void kernel_launch(void* const* d_in, const int* in_sizes, int n_in,
                              void* d_out, int out_size)
{
    const float2* Q = (const float2*)d_in[0];
    const float2* K = (const float2*)d_in[1];
    const float2* V = (const float2*)d_in[2];
    const float*  W = (const float*)d_in[3];
    const float*  bb = (const float*)d_in[4];
    float2* O = (float2*)d_out;

    static bool attr_set = false;
    if (!attr_set) {
        cudaFuncSetAttribute(attn_k, cudaFuncAttributeMaxDynamicSharedMemorySize, SMB);
        attr_set = true;
    }

    attn_k<<<dim3(32, 4), NT, SMB>>>(Q, K, V, W, bb, O);
}